// round 13
// baseline (speedup 1.0000x reference)
#include <cuda_runtime.h>

// Reference semantics: image (B,M,N,2) raw-reinterpreted as (2B,M,N) planes;
// flow2[p] = flow[p>>1]; out[p*MN + y*N + x] = bilinear(plane p, x+dx, y+dy),
// zero outside bounds.
// R7 mapping (block = 4 rows of one batch, blockDim=384, x=threadIdx.x, no
// per-pixel div/mod) + QUAD GATHER: the two x-corners land in one 16B-aligned
// float4 unless xc0%4==3, so each (sample-row, plane) needs one LDG.128 plus a
// rare predicated scalar fix-up. x-weights live in a 4-vector wq so corner
// selection is FMA dot-product, not dynamic extraction.

#define MM 384
#define NN 384
#define MN (MM * NN)
#define ROWS 4

__global__ __launch_bounds__(384) void warp_kernel(
    const float*  __restrict__ image,  // 2B*MN floats (raw)
    const float2* __restrict__ flow,   // B*MN float2
    float*        __restrict__ out)    // 2B*MN floats (raw)
{
    int bid = blockIdx.x;
    int b   = bid / 96;              // uniform per block
    int y0  = (bid - b * 96) * ROWS;
    int x   = threadIdx.x;

    const size_t pbase = (size_t)(2 * b) * MN;
    const float* pA = image + pbase;
    const float* pB = pA + MN;
    const float2* frow = flow + (size_t)b * MN + y0 * NN + x;
    float* oA = out + pbase + y0 * NN + x;
    float* oB = oA + MN;

#pragma unroll
    for (int i = 0; i < ROWS; i++) {
        float2 f = __ldcs(frow + i * NN);

        float xs = (float)x + f.x;
        float ys = (float)(y0 + i) + f.y;

        float x0f = floorf(xs);
        float y0f = floorf(ys);
        float wx = xs - x0f;
        float wy = ys - y0f;
        int xi0 = (int)x0f;
        int yi0 = (int)y0f;
        int xi1 = xi0 + 1;
        int yi1 = yi0 + 1;

        float wxm0 = ((unsigned)xi0 < (unsigned)NN) ? (1.0f - wx) : 0.0f;
        float wxm1 = ((unsigned)xi1 < (unsigned)NN) ? wx : 0.0f;
        float wym0 = ((unsigned)yi0 < (unsigned)MM) ? (1.0f - wy) : 0.0f;
        float wym1 = ((unsigned)yi1 < (unsigned)MM) ? wy : 0.0f;

        int xc0 = min(max(xi0, 0), NN - 1);
        int xc1 = min(max(xi1, 0), NN - 1);
        int yc0 = min(max(yi0, 0), MM - 1);
        int yc1 = min(max(yi1, 0), MM - 1);

        int quad = xc0 & ~3;         // 16B-aligned column group, always in-bounds
        int i0   = xc0 & 3;          // 0..3
        int i1   = xc1 - quad;       // 0..4 (4 => straddles into next quad)

        // x-weight vector over the quad (shared by both rows and both planes)
        float wq0 = ((i0 == 0) ? wxm0 : 0.0f) + ((i1 == 0) ? wxm1 : 0.0f);
        float wq1 = ((i0 == 1) ? wxm0 : 0.0f) + ((i1 == 1) ? wxm1 : 0.0f);
        float wq2 = ((i0 == 2) ? wxm0 : 0.0f) + ((i1 == 2) ? wxm1 : 0.0f);
        float wq3 = ((i0 == 3) ? wxm0 : 0.0f) + ((i1 == 3) ? wxm1 : 0.0f);

        const float* rA0 = pA + yc0 * NN;
        const float* rA1 = pA + yc1 * NN;
        const float* rB0 = pB + yc0 * NN;
        const float* rB1 = pB + yc1 * NN;

        // 4 vector gathers (independent -> MLP)
        float4 qA0 = __ldg((const float4*)(rA0 + quad));
        float4 qA1 = __ldg((const float4*)(rA1 + quad));
        float4 qB0 = __ldg((const float4*)(rB0 + quad));
        float4 qB1 = __ldg((const float4*)(rB1 + quad));

        float dA0 = qA0.x * wq0 + qA0.y * wq1 + qA0.z * wq2 + qA0.w * wq3;
        float dA1 = qA1.x * wq0 + qA1.y * wq1 + qA1.z * wq2 + qA1.w * wq3;
        float dB0 = qB0.x * wq0 + qB0.y * wq1 + qB0.z * wq2 + qB0.w * wq3;
        float dB1 = qB1.x * wq0 + qB1.y * wq1 + qB1.z * wq2 + qB1.w * wq3;

        if (i1 == 4) {               // straddle: x1 sits in the next quad (~25% lanes)
            dA0 += __ldg(rA0 + xc1) * wxm1;
            dA1 += __ldg(rA1 + xc1) * wxm1;
            dB0 += __ldg(rB0 + xc1) * wxm1;
            dB1 += __ldg(rB1 + xc1) * wxm1;
        }

        float accA = wym0 * dA0 + wym1 * dA1;
        float accB = wym0 * dB0 + wym1 * dB1;

        __stcs(oA + i * NN, accA);
        __stcs(oB + i * NN, accB);
    }
}

extern "C" void kernel_launch(void* const* d_in, const int* in_sizes, int n_in,
                              void* d_out, int out_size)
{
    const float*  image = (const float*)d_in[0];
    const float2* flow  = (const float2*)d_in[1];
    float* out = (float*)d_out;

    int B = out_size / (2 * MN);
    int blocks = B * (MM / ROWS);   // 64 * 96 = 6144
    warp_kernel<<<blocks, 384>>>(image, flow, out);
}

// round 14
// speedup vs baseline: 1.5478x; 1.5478x over previous
#include <cuda_runtime.h>

// Reference semantics: image (B,M,N,2) raw-reinterpreted as (2B,M,N) planes;
// flow2[p] = flow[p>>1]; out[p*MN + y*N + x] = bilinear(plane p, x+dx, y+dy),
// zero outside bounds. Row-aligned mapping: block = 4 rows of one batch,
// blockDim = 384 (one row), x = threadIdx.x, no per-pixel div/mod.
// __launch_bounds__(384, 4): 42-reg budget (vs 32 occupancy-capped) so more of
// the 32 written-out gathers are genuinely in flight; 4 blocks/SM = 75% occ.

#define MM 384
#define NN 384
#define MN (MM * NN)
#define ROWS 4

__global__ __launch_bounds__(384, 4) void warp_kernel(
    const float*  __restrict__ image,  // 2B*MN floats (raw)
    const float2* __restrict__ flow,   // B*MN float2
    float*        __restrict__ out)    // 2B*MN floats (raw)
{
    int bid = blockIdx.x;
    int b   = bid / 96;            // uniform per block
    int y0  = (bid - b * 96) * ROWS;
    int x   = threadIdx.x;

    const size_t pbase = (size_t)(2 * b) * MN;        // plane-A base
    const float2* frow = flow + (size_t)b * MN + y0 * NN + x;

    // flow loads for 4 rows (independent, streaming)
    float2 f[ROWS];
#pragma unroll
    for (int i = 0; i < ROWS; i++)
        f[i] = __ldcs(frow + i * NN);

    int   o00[ROWS], o01[ROWS], o10[ROWS], o11[ROWS];
    float w00[ROWS], w01[ROWS], w10[ROWS], w11[ROWS];

#pragma unroll
    for (int i = 0; i < ROWS; i++) {
        float xs = (float)x + f[i].x;
        float ys = (float)(y0 + i) + f[i].y;

        float x0f = floorf(xs);
        float y0f = floorf(ys);
        float wx = xs - x0f;
        float wy = ys - y0f;
        int xi0 = (int)x0f;
        int yi0 = (int)y0f;
        int xi1 = xi0 + 1;
        int yi1 = yi0 + 1;

        float wxm0 = ((unsigned)xi0 < (unsigned)NN) ? (1.0f - wx) : 0.0f;
        float wxm1 = ((unsigned)xi1 < (unsigned)NN) ? wx : 0.0f;
        float wym0 = ((unsigned)yi0 < (unsigned)MM) ? (1.0f - wy) : 0.0f;
        float wym1 = ((unsigned)yi1 < (unsigned)MM) ? wy : 0.0f;

        int xc0 = min(max(xi0, 0), NN - 1);
        int xc1 = min(max(xi1, 0), NN - 1);
        int yc0 = min(max(yi0, 0), MM - 1);
        int yc1 = min(max(yi1, 0), MM - 1);

        o00[i] = yc0 * NN + xc0;
        o01[i] = yc0 * NN + xc1;
        o10[i] = yc1 * NN + xc0;
        o11[i] = yc1 * NN + xc1;
        w00[i] = wym0 * wxm0;
        w01[i] = wym0 * wxm1;
        w10[i] = wym1 * wxm0;
        w11[i] = wym1 * wxm1;
    }

    const float* pA = image + pbase;
    const float* pB = pA + MN;

    // front-batch all 32 gathers (register budget now allows deeper batching)
    float vA00[ROWS], vA01[ROWS], vA10[ROWS], vA11[ROWS];
    float vB00[ROWS], vB01[ROWS], vB10[ROWS], vB11[ROWS];
#pragma unroll
    for (int i = 0; i < ROWS; i++) {
        vA00[i] = __ldg(pA + o00[i]);
        vA01[i] = __ldg(pA + o01[i]);
        vA10[i] = __ldg(pA + o10[i]);
        vA11[i] = __ldg(pA + o11[i]);
        vB00[i] = __ldg(pB + o00[i]);
        vB01[i] = __ldg(pB + o01[i]);
        vB10[i] = __ldg(pB + o10[i]);
        vB11[i] = __ldg(pB + o11[i]);
    }

    float* oA = out + pbase + y0 * NN + x;
    float* oB = oA + MN;
#pragma unroll
    for (int i = 0; i < ROWS; i++) {
        float accA = vA00[i] * w00[i] + vA01[i] * w01[i]
                   + vA10[i] * w10[i] + vA11[i] * w11[i];
        float accB = vB00[i] * w00[i] + vB01[i] * w01[i]
                   + vB10[i] * w10[i] + vB11[i] * w11[i];
        __stcs(oA + i * NN, accA);
        __stcs(oB + i * NN, accB);
    }
}

extern "C" void kernel_launch(void* const* d_in, const int* in_sizes, int n_in,
                              void* d_out, int out_size)
{
    const float*  image = (const float*)d_in[0];
    const float2* flow  = (const float2*)d_in[1];
    float* out = (float*)d_out;

    int B = out_size / (2 * MN);
    int blocks = B * (MM / ROWS);   // 64 * 96 = 6144
    warp_kernel<<<blocks, 384>>>(image, flow, out);
}